// round 6
// baseline (speedup 1.0000x reference)
#include <cuda_runtime.h>
#include <cstdint>

#define MAX_NODES 100000
#define MAX_EDGES 1600000
#define D_FEAT 64
#define SCAN_BLOCK 512
#define MAX_SCAN_BLOCKS 256

// ---- scratch (zero at module load; place_kernel restores the zero invariant
//      for g_cnt / g_desc at the end of every run) ----
__device__ unsigned int       g_cnt        [MAX_NODES];
__device__ unsigned int       g_offsets    [MAX_NODES + 1];
__device__ unsigned long long g_desc       [MAX_SCAN_BLOCKS];
__device__ int                g_rank       [MAX_EDGES];
__device__ int                g_edge_sorted[MAX_EDGES];

#define FLAG_INVALID 0ull
#define FLAG_AGG     1ull
#define FLAG_INC     2ull
__device__ __forceinline__ unsigned long long pack_desc(unsigned long long flag, unsigned int v) {
    return (flag << 32) | (unsigned long long)v;
}

// ---------------- pass 1: rank (the only atomic pass) ----------------
__global__ void rank_kernel(const int* __restrict__ dst, int n_edges, int n_nodes) {
    int i4 = blockIdx.x * blockDim.x + threadIdx.x;
    int base = i4 * 4;
    if (base + 3 < n_edges) {
        int4 d = ((const int4*)dst)[i4];
        int4 r;
        r.x = ((unsigned)d.x < (unsigned)n_nodes) ? (int)atomicAdd(&g_cnt[d.x], 1u) : 0;
        r.y = ((unsigned)d.y < (unsigned)n_nodes) ? (int)atomicAdd(&g_cnt[d.y], 1u) : 0;
        r.z = ((unsigned)d.z < (unsigned)n_nodes) ? (int)atomicAdd(&g_cnt[d.z], 1u) : 0;
        r.w = ((unsigned)d.w < (unsigned)n_nodes) ? (int)atomicAdd(&g_cnt[d.w], 1u) : 0;
        ((int4*)g_rank)[i4] = r;
    } else {
        for (int e = base; e < n_edges; e++) {
            int d = dst[e];
            g_rank[e] = ((unsigned)d < (unsigned)n_nodes)
                      ? (int)atomicAdd(&g_cnt[d], 1u) : 0;
        }
    }
}

// ---------------- pass 2: decoupled-lookback exclusive scan ----------------
__global__ void __launch_bounds__(SCAN_BLOCK)
scan_lookback_kernel(int n_nodes, int n_edges) {
    __shared__ unsigned int sm_warp_tot[16];
    __shared__ unsigned int sm_excl_prefix;
    __shared__ unsigned int sm_agg;

    int tid  = threadIdx.x;
    int lane = tid & 31;
    int wid  = tid >> 5;
    int gi   = blockIdx.x * SCAN_BLOCK + tid;

    unsigned int v = (gi < n_nodes) ? g_cnt[gi] : 0u;

    unsigned int inc = v;
    #pragma unroll
    for (int off = 1; off < 32; off <<= 1) {
        unsigned int t = __shfl_up_sync(0xffffffffu, inc, off);
        if (lane >= off) inc += t;
    }
    if (lane == 31) sm_warp_tot[wid] = inc;
    __syncthreads();

    if (wid == 0) {
        unsigned int w = (lane < 16) ? sm_warp_tot[lane] : 0u;
        unsigned int winc = w;
        #pragma unroll
        for (int off = 1; off < 16; off <<= 1) {
            unsigned int t = __shfl_up_sync(0xffffffffu, winc, off);
            if (lane >= off) winc += t;
        }
        if (lane < 16) sm_warp_tot[lane] = winc - w;
    }
    __syncthreads();

    unsigned int local_excl = sm_warp_tot[wid] + inc - v;
    if (tid == SCAN_BLOCK - 1) sm_agg = sm_warp_tot[15] + inc;
    __syncthreads();
    unsigned int block_agg = sm_agg;

    if (tid == 0) {
        unsigned long long d = (blockIdx.x == 0)
            ? pack_desc(FLAG_INC, block_agg)
            : pack_desc(FLAG_AGG, block_agg);
        __threadfence();
        atomicExch(&g_desc[blockIdx.x], d);
    }

    if (blockIdx.x == 0) {
        if (tid == 0) sm_excl_prefix = 0u;
    } else if (wid == 0) {
        unsigned int excl = 0u;
        int start = (int)blockIdx.x - 1;
        while (true) {
            int idx = start - lane;
            unsigned long long d;
            unsigned long long f;
            do {
                d = (idx >= 0) ? atomicAdd(&g_desc[idx], 0ull)
                               : pack_desc(FLAG_AGG, 0u);
                f = d >> 32;
            } while (__any_sync(0xffffffffu, f == FLAG_INVALID));
            unsigned int val = (unsigned int)d;
            unsigned int incmask = __ballot_sync(0xffffffffu, (idx >= 0) && f == FLAG_INC);
            unsigned int contrib;
            if (incmask) {
                int inc_lane = __ffs(incmask) - 1;
                contrib = (lane <= inc_lane) ? val : 0u;
            } else {
                contrib = (idx >= 0) ? val : 0u;
            }
            #pragma unroll
            for (int off = 16; off > 0; off >>= 1)
                contrib += __shfl_xor_sync(0xffffffffu, contrib, off);
            excl += contrib;
            if (incmask) break;
            start -= 32;
        }
        if (lane == 0) {
            sm_excl_prefix = excl;
            __threadfence();
            atomicExch(&g_desc[blockIdx.x], pack_desc(FLAG_INC, excl + block_agg));
        }
    }
    __syncthreads();
    unsigned int excl_prefix = sm_excl_prefix;

    if (gi < n_nodes) g_offsets[gi] = excl_prefix + local_excl;
    if (gi == 0)      g_offsets[n_nodes] = (unsigned int)n_edges;
}

// ---------------- pass 3: place (atomic-free) + cleanup ----------------
__global__ void place_kernel(const int* __restrict__ dst, int n_edges, int n_nodes) {
    int i4 = blockIdx.x * blockDim.x + threadIdx.x;
    int base = i4 * 4;
    if (base + 3 < n_edges) {
        int4 d = ((const int4*)dst)[i4];
        int4 r = ((const int4*)g_rank)[i4];
        if ((unsigned)d.x < (unsigned)n_nodes) g_edge_sorted[g_offsets[d.x] + r.x] = base;
        if ((unsigned)d.y < (unsigned)n_nodes) g_edge_sorted[g_offsets[d.y] + r.y] = base + 1;
        if ((unsigned)d.z < (unsigned)n_nodes) g_edge_sorted[g_offsets[d.z] + r.z] = base + 2;
        if ((unsigned)d.w < (unsigned)n_nodes) g_edge_sorted[g_offsets[d.w] + r.w] = base + 3;
    } else {
        for (int e = base; e < n_edges; e++) {
            int d = dst[e];
            if ((unsigned)d < (unsigned)n_nodes)
                g_edge_sorted[g_offsets[d] + g_rank[e]] = e;
        }
    }
    int t = blockIdx.x * blockDim.x + threadIdx.x;
    if (t < n_nodes) g_cnt[t] = 0u;
    if (t < MAX_SCAN_BLOCKS) g_desc[t] = FLAG_INVALID;
}

// ---------------- pass 4: gather ----------------
// One warp per node; lane l owns feature columns [2l, 2l+2) (float2) for the
// whole segment -> no cross-lane reduction. Edge ids are staged 32-at-a-time
// into registers via ONE coalesced load per chunk and broadcast with shfl, so
// the row loads in the inner loop are mutually independent (deep MLP).
__global__ void gather_kernel(const float2* __restrict__ msg,
                              float* __restrict__ out, int n_nodes) {
    int warp_id = (blockIdx.x * blockDim.x + threadIdx.x) >> 5;
    if (warp_id >= n_nodes) return;
    int lane = threadIdx.x & 31;

    unsigned int start = g_offsets[warp_id];
    unsigned int end   = g_offsets[warp_id + 1];
    unsigned int deg   = end - start;

    const float NEG_INF = -__int_as_float(0x7f800000);
    float2 s  = {0.f, 0.f};
    float2 q  = {0.f, 0.f};
    float2 mx = {NEG_INF, NEG_INF};

    unsigned int base = start;
    while (base < end) {
        unsigned int rem = end - base;
        unsigned int cnt = rem < 32u ? rem : 32u;
        // one coalesced id load per 32 edges (clamped: stays inside segment)
        unsigned int idx = base + (unsigned)lane;
        int myid = g_edge_sorted[idx < end ? idx : end - 1];

        #pragma unroll 8
        for (unsigned int j = 0; j < cnt; j++) {
            int e = __shfl_sync(0xffffffffu, myid, j);
            float2 m = __ldcs(msg + (size_t)e * 32 + lane);
            s.x += m.x;         s.y += m.y;
            q.x += m.x * m.x;   q.y += m.y * m.y;
            mx.x = fmaxf(mx.x, m.x);
            mx.y = fmaxf(mx.y, m.y);
        }
        base += cnt;
    }

    float degf = deg ? (float)deg : 1.0f;
    float inv  = 1.0f / degf;
    float2 mean = {s.x * inv, s.y * inv};
    float2 sd;
    sd.x = sqrtf(fmaxf(q.x * inv - mean.x * mean.x, 0.0f) + 1e-8f);
    sd.y = sqrtf(fmaxf(q.y * inv - mean.y * mean.y, 0.0f) + 1e-8f);
    if (deg == 0) { mx.x = 0.0f; mx.y = 0.0f; }

    // output row: [sum(64) | mean(64) | max(64) | std(64)]
    float2* row = (float2*)(out + (size_t)warp_id * (4 * D_FEAT));
    __stcs(row + lane,      s);
    __stcs(row + 32 + lane, mean);
    __stcs(row + 64 + lane, mx);
    __stcs(row + 96 + lane, sd);
}

extern "C" void kernel_launch(void* const* d_in, const int* in_sizes, int n_in,
                              void* d_out, int out_size) {
    const float* msg = (const float*)d_in[0];
    const int*   dst = (const int*)d_in[1];
    int n_edges = in_sizes[1];
    if (n_edges > MAX_EDGES) n_edges = MAX_EDGES;
    int n_nodes = out_size / (4 * D_FEAT);
    if (n_nodes > MAX_NODES) n_nodes = MAX_NODES;

    int scan_blocks = (n_nodes + SCAN_BLOCK - 1) / SCAN_BLOCK;
    int quads = (n_edges + 3) / 4;

    rank_kernel<<<(quads + 255) / 256, 256>>>(dst, n_edges, n_nodes);
    scan_lookback_kernel<<<scan_blocks, SCAN_BLOCK>>>(n_nodes, n_edges);
    place_kernel<<<(quads + 255) / 256, 256>>>(dst, n_edges, n_nodes);

    int gather_blocks = (n_nodes * 32 + 255) / 256;
    gather_kernel<<<gather_blocks, 256>>>((const float2*)msg, (float*)d_out, n_nodes);
}

// round 7
// speedup vs baseline: 1.0458x; 1.0458x over previous
#include <cuda_runtime.h>
#include <cstdint>

#define MAX_NODES 100000
#define MAX_EDGES 1600000
#define D_FEAT 64
#define SCAN_BLOCK 512
#define MAX_SCAN_BLOCKS 256

// ---- scratch (zero at module load; place_kernel restores the zero invariant
//      for g_cnt / g_desc at the end of every run) ----
__device__ unsigned int       g_cnt        [MAX_NODES];
__device__ unsigned int       g_offsets    [MAX_NODES + 1];
__device__ unsigned long long g_desc       [MAX_SCAN_BLOCKS];
__device__ int                g_rank       [MAX_EDGES];
__device__ int                g_edge_sorted[MAX_EDGES];

#define FLAG_INVALID 0ull
#define FLAG_AGG     1ull
#define FLAG_INC     2ull
__device__ __forceinline__ unsigned long long pack_desc(unsigned long long flag, unsigned int v) {
    return (flag << 32) | (unsigned long long)v;
}

// ---------------- pass 1: rank (the only atomic pass) ----------------
__global__ void rank_kernel(const int* __restrict__ dst, int n_edges, int n_nodes) {
    int i4 = blockIdx.x * blockDim.x + threadIdx.x;
    int base = i4 * 4;
    if (base + 3 < n_edges) {
        int4 d = ((const int4*)dst)[i4];
        int4 r;
        r.x = ((unsigned)d.x < (unsigned)n_nodes) ? (int)atomicAdd(&g_cnt[d.x], 1u) : 0;
        r.y = ((unsigned)d.y < (unsigned)n_nodes) ? (int)atomicAdd(&g_cnt[d.y], 1u) : 0;
        r.z = ((unsigned)d.z < (unsigned)n_nodes) ? (int)atomicAdd(&g_cnt[d.z], 1u) : 0;
        r.w = ((unsigned)d.w < (unsigned)n_nodes) ? (int)atomicAdd(&g_cnt[d.w], 1u) : 0;
        ((int4*)g_rank)[i4] = r;
    } else {
        for (int e = base; e < n_edges; e++) {
            int d = dst[e];
            g_rank[e] = ((unsigned)d < (unsigned)n_nodes)
                      ? (int)atomicAdd(&g_cnt[d], 1u) : 0;
        }
    }
}

// ---------------- pass 2: decoupled-lookback exclusive scan ----------------
__global__ void __launch_bounds__(SCAN_BLOCK)
scan_lookback_kernel(int n_nodes, int n_edges) {
    __shared__ unsigned int sm_warp_tot[16];
    __shared__ unsigned int sm_excl_prefix;
    __shared__ unsigned int sm_agg;

    int tid  = threadIdx.x;
    int lane = tid & 31;
    int wid  = tid >> 5;
    int gi   = blockIdx.x * SCAN_BLOCK + tid;

    unsigned int v = (gi < n_nodes) ? g_cnt[gi] : 0u;

    unsigned int inc = v;
    #pragma unroll
    for (int off = 1; off < 32; off <<= 1) {
        unsigned int t = __shfl_up_sync(0xffffffffu, inc, off);
        if (lane >= off) inc += t;
    }
    if (lane == 31) sm_warp_tot[wid] = inc;
    __syncthreads();

    if (wid == 0) {
        unsigned int w = (lane < 16) ? sm_warp_tot[lane] : 0u;
        unsigned int winc = w;
        #pragma unroll
        for (int off = 1; off < 16; off <<= 1) {
            unsigned int t = __shfl_up_sync(0xffffffffu, winc, off);
            if (lane >= off) winc += t;
        }
        if (lane < 16) sm_warp_tot[lane] = winc - w;
    }
    __syncthreads();

    unsigned int local_excl = sm_warp_tot[wid] + inc - v;
    if (tid == SCAN_BLOCK - 1) sm_agg = sm_warp_tot[15] + inc;
    __syncthreads();
    unsigned int block_agg = sm_agg;

    if (tid == 0) {
        unsigned long long d = (blockIdx.x == 0)
            ? pack_desc(FLAG_INC, block_agg)
            : pack_desc(FLAG_AGG, block_agg);
        __threadfence();
        atomicExch(&g_desc[blockIdx.x], d);
    }

    if (blockIdx.x == 0) {
        if (tid == 0) sm_excl_prefix = 0u;
    } else if (wid == 0) {
        unsigned int excl = 0u;
        int start = (int)blockIdx.x - 1;
        while (true) {
            int idx = start - lane;
            unsigned long long d;
            unsigned long long f;
            do {
                d = (idx >= 0) ? atomicAdd(&g_desc[idx], 0ull)
                               : pack_desc(FLAG_AGG, 0u);
                f = d >> 32;
            } while (__any_sync(0xffffffffu, f == FLAG_INVALID));
            unsigned int val = (unsigned int)d;
            unsigned int incmask = __ballot_sync(0xffffffffu, (idx >= 0) && f == FLAG_INC);
            unsigned int contrib;
            if (incmask) {
                int inc_lane = __ffs(incmask) - 1;
                contrib = (lane <= inc_lane) ? val : 0u;
            } else {
                contrib = (idx >= 0) ? val : 0u;
            }
            #pragma unroll
            for (int off = 16; off > 0; off >>= 1)
                contrib += __shfl_xor_sync(0xffffffffu, contrib, off);
            excl += contrib;
            if (incmask) break;
            start -= 32;
        }
        if (lane == 0) {
            sm_excl_prefix = excl;
            __threadfence();
            atomicExch(&g_desc[blockIdx.x], pack_desc(FLAG_INC, excl + block_agg));
        }
    }
    __syncthreads();
    unsigned int excl_prefix = sm_excl_prefix;

    if (gi < n_nodes) g_offsets[gi] = excl_prefix + local_excl;
    if (gi == 0)      g_offsets[n_nodes] = (unsigned int)n_edges;
}

// ---------------- pass 3: place (atomic-free) + cleanup ----------------
__global__ void place_kernel(const int* __restrict__ dst, int n_edges, int n_nodes) {
    int i4 = blockIdx.x * blockDim.x + threadIdx.x;
    int base = i4 * 4;
    if (base + 3 < n_edges) {
        int4 d = ((const int4*)dst)[i4];
        int4 r = ((const int4*)g_rank)[i4];
        if ((unsigned)d.x < (unsigned)n_nodes) g_edge_sorted[g_offsets[d.x] + r.x] = base;
        if ((unsigned)d.y < (unsigned)n_nodes) g_edge_sorted[g_offsets[d.y] + r.y] = base + 1;
        if ((unsigned)d.z < (unsigned)n_nodes) g_edge_sorted[g_offsets[d.z] + r.z] = base + 2;
        if ((unsigned)d.w < (unsigned)n_nodes) g_edge_sorted[g_offsets[d.w] + r.w] = base + 3;
    } else {
        for (int e = base; e < n_edges; e++) {
            int d = dst[e];
            if ((unsigned)d < (unsigned)n_nodes)
                g_edge_sorted[g_offsets[d] + g_rank[e]] = e;
        }
    }
    int t = blockIdx.x * blockDim.x + threadIdx.x;
    if (t < n_nodes) g_cnt[t] = 0u;
    if (t < MAX_SCAN_BLOCKS) g_desc[t] = FLAG_INVALID;
}

// ---------------- pass 4: gather (R5 structure, 8-deep MLP) ----------------
// One warp per node; each half-warp streams one edge row per step (16 lanes x
// float4 = 256B coalesced). Up to 8 independent row loads in flight per
// half-warp. Edge-id loads hit L1 (sequential within segment).
__global__ void gather_kernel(const float4* __restrict__ msg,
                              float* __restrict__ out, int n_nodes) {
    int warp_id = (blockIdx.x * blockDim.x + threadIdx.x) >> 5;
    if (warp_id >= n_nodes) return;
    int lane = threadIdx.x & 31;
    int half = lane >> 4;
    int c    = lane & 15;

    unsigned int start = g_offsets[warp_id];
    unsigned int end   = g_offsets[warp_id + 1];
    unsigned int deg   = end - start;

    const float NEG_INF = -__int_as_float(0x7f800000);
    float4 s  = {0.f, 0.f, 0.f, 0.f};
    float4 q  = {0.f, 0.f, 0.f, 0.f};
    float4 mx = {NEG_INF, NEG_INF, NEG_INF, NEG_INF};

    unsigned int i = start + half;
    // 8 independent edge rows in flight per half-warp
    for (; i + 14 < end; i += 16) {
        int eids[8];
        #pragma unroll
        for (int u = 0; u < 8; u++) eids[u] = g_edge_sorted[i + 2 * u];
        float4 m[8];
        #pragma unroll
        for (int u = 0; u < 8; u++) m[u] = __ldcs(msg + (size_t)eids[u] * 16 + c);
        #pragma unroll
        for (int u = 0; u < 8; u++) {
            s.x += m[u].x; s.y += m[u].y; s.z += m[u].z; s.w += m[u].w;
            q.x += m[u].x * m[u].x; q.y += m[u].y * m[u].y;
            q.z += m[u].z * m[u].z; q.w += m[u].w * m[u].w;
            mx.x = fmaxf(mx.x, m[u].x); mx.y = fmaxf(mx.y, m[u].y);
            mx.z = fmaxf(mx.z, m[u].z); mx.w = fmaxf(mx.w, m[u].w);
        }
    }
    // tail: 2 in flight
    for (; i + 2 < end; i += 4) {
        int e0 = g_edge_sorted[i];
        int e1 = g_edge_sorted[i + 2];
        float4 m0 = __ldcs(msg + (size_t)e0 * 16 + c);
        float4 m1 = __ldcs(msg + (size_t)e1 * 16 + c);
        s.x += m0.x + m1.x; s.y += m0.y + m1.y;
        s.z += m0.z + m1.z; s.w += m0.w + m1.w;
        q.x += m0.x*m0.x + m1.x*m1.x; q.y += m0.y*m0.y + m1.y*m1.y;
        q.z += m0.z*m0.z + m1.z*m1.z; q.w += m0.w*m0.w + m1.w*m1.w;
        mx.x = fmaxf(mx.x, fmaxf(m0.x, m1.x)); mx.y = fmaxf(mx.y, fmaxf(m0.y, m1.y));
        mx.z = fmaxf(mx.z, fmaxf(m0.z, m1.z)); mx.w = fmaxf(mx.w, fmaxf(m0.w, m1.w));
    }
    for (; i < end; i += 2) {
        int e = g_edge_sorted[i];
        float4 m = __ldcs(msg + (size_t)e * 16 + c);
        s.x += m.x;       s.y += m.y;       s.z += m.z;       s.w += m.w;
        q.x += m.x * m.x; q.y += m.y * m.y; q.z += m.z * m.z; q.w += m.w * m.w;
        mx.x = fmaxf(mx.x, m.x); mx.y = fmaxf(mx.y, m.y);
        mx.z = fmaxf(mx.z, m.z); mx.w = fmaxf(mx.w, m.w);
    }

    const unsigned FULL = 0xffffffffu;
    s.x += __shfl_xor_sync(FULL, s.x, 16); s.y += __shfl_xor_sync(FULL, s.y, 16);
    s.z += __shfl_xor_sync(FULL, s.z, 16); s.w += __shfl_xor_sync(FULL, s.w, 16);
    q.x += __shfl_xor_sync(FULL, q.x, 16); q.y += __shfl_xor_sync(FULL, q.y, 16);
    q.z += __shfl_xor_sync(FULL, q.z, 16); q.w += __shfl_xor_sync(FULL, q.w, 16);
    mx.x = fmaxf(mx.x, __shfl_xor_sync(FULL, mx.x, 16));
    mx.y = fmaxf(mx.y, __shfl_xor_sync(FULL, mx.y, 16));
    mx.z = fmaxf(mx.z, __shfl_xor_sync(FULL, mx.z, 16));
    mx.w = fmaxf(mx.w, __shfl_xor_sync(FULL, mx.w, 16));

    float degf = deg ? (float)deg : 1.0f;
    float inv  = 1.0f / degf;
    float4 mean = {s.x * inv, s.y * inv, s.z * inv, s.w * inv};
    float4 sd;
    sd.x = sqrtf(fmaxf(q.x * inv - mean.x * mean.x, 0.0f) + 1e-8f);
    sd.y = sqrtf(fmaxf(q.y * inv - mean.y * mean.y, 0.0f) + 1e-8f);
    sd.z = sqrtf(fmaxf(q.z * inv - mean.z * mean.z, 0.0f) + 1e-8f);
    sd.w = sqrtf(fmaxf(q.w * inv - mean.w * mean.w, 0.0f) + 1e-8f);
    if (deg == 0) { mx.x = mx.y = mx.z = mx.w = 0.0f; }

    float4* row = (float4*)(out + (size_t)warp_id * (4 * D_FEAT));
    if (half == 0) {
        __stcs(row + c,      s);    // sum  [0..64)
        __stcs(row + 32 + c, mx);   // max  [128..192)
    } else {
        __stcs(row + 16 + c, mean); // mean [64..128)
        __stcs(row + 48 + c, sd);   // std  [192..256)
    }
}

extern "C" void kernel_launch(void* const* d_in, const int* in_sizes, int n_in,
                              void* d_out, int out_size) {
    const float* msg = (const float*)d_in[0];
    const int*   dst = (const int*)d_in[1];
    int n_edges = in_sizes[1];
    if (n_edges > MAX_EDGES) n_edges = MAX_EDGES;
    int n_nodes = out_size / (4 * D_FEAT);
    if (n_nodes > MAX_NODES) n_nodes = MAX_NODES;

    int scan_blocks = (n_nodes + SCAN_BLOCK - 1) / SCAN_BLOCK;
    int quads = (n_edges + 3) / 4;

    rank_kernel<<<(quads + 255) / 256, 256>>>(dst, n_edges, n_nodes);
    scan_lookback_kernel<<<scan_blocks, SCAN_BLOCK>>>(n_nodes, n_edges);
    place_kernel<<<(quads + 255) / 256, 256>>>(dst, n_edges, n_nodes);

    int gather_blocks = (n_nodes * 32 + 255) / 256;
    gather_kernel<<<gather_blocks, 256>>>((const float4*)msg, (float*)d_out, n_nodes);
}